// round 14
// baseline (speedup 1.0000x reference)
#include <cuda_runtime.h>

// Blur: depthwise 4x4 FIR (separable [1,3,3,1] ⊗ [1,3,3,1] / 16), pad (1,1).
// Input (4,128,513,513) f32 -> Output (4,128,512,512) f32.
//
// Round-14: burst-oriented full-width blocks. One 256-thread block owns a
// full-width 64-row strip of one plane. Per stage it loads 4 input rows =
// ONE contiguous 8.2KB gmem region (rows are contiguous within a plane) via
// dense unit-stride warp loads, and writes 4 output rows = one contiguous
// 8KB region. 3-slot smem ring (4 rows/slot), one __syncthreads per stage.
// Rows stored shifted +1 into 516-wide smem rows: pad cols (-1, 513, 514)
// are zero-filled slots, so the horizontal FIR is 3 mask-free aligned
// LDS.64 per row per thread. Vertical FIR over a 7-deep float2 window,
// 4 output rows (float2/thread) per stage.

#define W_IN   513
#define H_IN   513
#define W_OUT  512
#define H_OUT  512
#define STRIP  64
#define RW     516            // smem row width (513 data + pads), even, x0+5 < 516
#define NPLANE 512            // 4*128
#define NSTAGE 17             // rows y0-1 .. y0+66 in 4-row chunks

__global__ __launch_bounds__(256)
void blur_row4_kernel(const float* __restrict__ in, float* __restrict__ out)
{
    __shared__ float sbuf[3][4][RW];      // [ring slot][row][shifted col]  (24.2 KB)

    const int t     = threadIdx.x;        // 0..255
    const int plane = blockIdx.y;
    const int y0    = blockIdx.x * STRIP;
    const int x0    = t << 1;             // output cols x0, x0+1

    const float* ip = in  + (size_t)plane * (W_IN * H_IN);
    float*       op = out + (size_t)plane * (W_OUT * H_OUT);

    // Stage s: input rows rs..rs+3 (rs = y0-1+4s) into ring slot.
    // smem layout: col c of row dr at sbuf[slot][dr][c+1]; idx 0/514/515 = 0 pads.
    auto stage = [&](int s, int slot) {
        const int rs = y0 - 1 + 4 * s;
        #pragma unroll
        for (int dr = 0; dr < 4; ++dr) {
            const int g = rs + dr;
            float* __restrict__ sl = &sbuf[slot][dr][0];
            if ((unsigned)g < (unsigned)H_IN) {              // warp-uniform
                const float* __restrict__ rb = ip + (size_t)g * W_IN;
                float v0 = __ldg(rb + t);                    // cols 0..255
                float v1 = __ldg(rb + 256 + t);              // cols 256..511
                float v2 = (t == 0) ? __ldg(rb + 512) : 0.f; // col 512
                sl[t + 1]   = v0;
                sl[t + 257] = v1;
                if (t == 0) { sl[513] = v2; sl[0] = 0.f; }
                if (t == 1) { sl[514] = 0.f; sl[515] = 0.f; }
            } else {                                         // pad row -> zeros
                sl[t + 1]   = 0.f;
                sl[t + 257] = 0.f;
                if (t == 0) { sl[513] = 0.f; sl[0] = 0.f; }
                if (t == 1) { sl[514] = 0.f; sl[515] = 0.f; }
            }
        }
    };

    // Horizontal FIR for ring row dr: cols x0-1..x0+4 live at idx x0..x0+5.
    // Three aligned LDS.64, no masks (pads are zeros).
    auto hq = [&](int slot, int dr) -> float2 {
        const float* __restrict__ row = &sbuf[slot][dr][0] + x0;
        float2 A = *reinterpret_cast<const float2*>(row);      // cols x0-1, x0
        float2 B = *reinterpret_cast<const float2*>(row + 2);  // cols x0+1, x0+2
        float2 C = *reinterpret_cast<const float2*>(row + 4);  // cols x0+3, x0+4
        float2 h;
        h.x = A.x + 3.0f * (A.y + B.x) + B.y;
        h.y = A.y + 3.0f * (B.x + B.y) + C.x;
        return h;
    };

    auto fv = [](float2 a, float2 b, float2 c, float2 d) -> float2 {
        float2 o;
        o.x = (a.x + d.x + 3.0f * (b.x + c.x)) * 0.0625f;
        o.y = (a.y + d.y + 3.0f * (b.y + c.y)) * 0.0625f;
        return o;
    };

    // Prologue: stages 0,1 staged; consume stage 0 (emits 1 output row).
    stage(0, 0);
    stage(1, 1);
    __syncthreads();
    float2 hn0 = hq(0, 0), hn1 = hq(0, 1), hn2 = hq(0, 2), hn3 = hq(0, 3);
    *reinterpret_cast<float2*>(op + (size_t)y0 * W_OUT + x0) = fv(hn0, hn1, hn2, hn3);
    float2 hp0 = hn1, hp1 = hn2, hp2 = hn3;

    for (int s = 1; s < NSTAGE; ++s) {
        if (s < NSTAGE - 1) stage(s + 1, (s + 1) % 3);   // overlap with consume
        __syncthreads();
        const int slot = s % 3;
        hn0 = hq(slot, 0); hn1 = hq(slot, 1); hn2 = hq(slot, 2); hn3 = hq(slot, 3);

        float* o = op + (size_t)(y0 + 4 * s - 3) * W_OUT + x0;
        *reinterpret_cast<float2*>(o)             = fv(hp0, hp1, hp2, hn0);
        *reinterpret_cast<float2*>(o + W_OUT)     = fv(hp1, hp2, hn0, hn1);
        *reinterpret_cast<float2*>(o + 2 * W_OUT) = fv(hp2, hn0, hn1, hn2);
        if (s < NSTAGE - 1)
            *reinterpret_cast<float2*>(o + 3 * W_OUT) = fv(hn0, hn1, hn2, hn3);

        hp0 = hn1; hp1 = hn2; hp2 = hn3;
    }
}

extern "C" void kernel_launch(void* const* d_in, const int* in_sizes, int n_in,
                              void* d_out, int out_size)
{
    const float* in  = (const float*)d_in[0];
    float*       out = (float*)d_out;
    // d_in[1] is the 4x4 FIR buffer: fixed normalized [1,3,3,1] outer product
    // * factor^2 == ([1,3,3,1] ⊗ [1,3,3,1]) / 16, folded into the constants.

    dim3 grid(H_OUT / STRIP, NPLANE);   // (8, 512)
    blur_row4_kernel<<<grid, 256>>>(in, out);
}

// round 15
// speedup vs baseline: 1.3524x; 1.3524x over previous
#include <cuda_runtime.h>
#include <cstdint>

// Blur: depthwise 4x4 FIR (separable [1,3,3,1] ⊗ [1,3,3,1] / 16), pad (1,1).
// Input (4,128,513,513) f32 -> Output (4,128,512,512) f32.
//
// Round-15: hardware bulk-async staging. One 288-thread block owns a
// full-width 64-row strip. A producer thread issues ONE cp.async.bulk
// (UBLKCP) per input row into an 8-deep smem ring (2064B aligned superset:
// rows start at 16B-misaligned addresses; floor-align start, and
// (start&3)*4 + 2052 rounds to 2064 for every phase — constant size, and
// the final row of the tensor ends exactly at the buffer end).
// 8 consumer warps: mbarrier full-wait -> 5 scalar LDS + horizontal FIR
// (shift = start&3 floats) -> 4-deep vertical float2 ring -> STG.64 ->
// empty-arrive. Bytes in flight: 8 slots x 2KB x ~7 blocks/SM ≈ 115 KB/SM,
// issued off the SM critical path; reads bypass L1.

#define W_IN   513
#define H_IN   513
#define W_OUT  512
#define H_OUT  512
#define STRIP  64
#define NROWS  (STRIP + 3)    // 67 input rows per strip
#define SLOTW  528            // floats per ring slot (2112 B >= 2064 B copy)
#define NSLOT  8
#define NPLANE 512            // 4*128
#define CPBYTES 2064

__device__ __forceinline__ void mbar_init(uint32_t addr, uint32_t cnt) {
    asm volatile("mbarrier.init.shared.b64 [%0], %1;" :: "r"(addr), "r"(cnt) : "memory");
}
__device__ __forceinline__ void mbar_arrive(uint32_t addr) {
    asm volatile("mbarrier.arrive.shared.b64 _, [%0];" :: "r"(addr) : "memory");
}
__device__ __forceinline__ void mbar_arrive_tx(uint32_t addr, uint32_t bytes) {
    asm volatile("mbarrier.arrive.expect_tx.shared.b64 _, [%0], %1;"
                 :: "r"(addr), "r"(bytes) : "memory");
}
__device__ __forceinline__ void mbar_wait(uint32_t addr, uint32_t phase) {
    asm volatile(
        "{\n\t.reg .pred P;\n\t"
        "W_%=:\n\t"
        "mbarrier.try_wait.parity.acquire.cta.shared::cta.b64 P, [%0], %1, 0x989680;\n\t"
        "@!P bra W_%=;\n\t}"
        :: "r"(addr), "r"(phase) : "memory");
}
__device__ __forceinline__ void bulk_cp(uint32_t dst, const void* src,
                                        uint32_t bytes, uint32_t mbar) {
    asm volatile(
        "cp.async.bulk.shared::cta.global.mbarrier::complete_tx::bytes "
        "[%0], [%1], %2, [%3];"
        :: "r"(dst), "l"(src), "r"(bytes), "r"(mbar) : "memory");
}

__global__ __launch_bounds__(288)
void blur_bulk_kernel(const float* __restrict__ in, float* __restrict__ out)
{
    __shared__ __align__(16) float ring[NSLOT][SLOTW];           // 16.5 KB
    __shared__ __align__(8)  unsigned long long mbar[2 * NSLOT]; // full[0..7], empty[8..15]

    const int t     = threadIdx.x;         // 0..287; warps 0..7 consume, warp 8 produces
    const int plane = blockIdx.y;
    const int y0    = blockIdx.x * STRIP;

    const size_t bp = (size_t)plane * (W_IN * H_IN);
    float* op = out + (size_t)plane * (W_OUT * H_OUT);

    const uint32_t ring0 = (uint32_t)__cvta_generic_to_shared(&ring[0][0]);
    const uint32_t mb0   = (uint32_t)__cvta_generic_to_shared(&mbar[0]);
    auto full_a  = [&](int s) { return mb0 + (uint32_t)(s * 8); };
    auto empty_a = [&](int s) { return mb0 + (uint32_t)((NSLOT + s) * 8); };

    if (t == 0) {
        #pragma unroll
        for (int s = 0; s < NSLOT; ++s) {
            mbar_init(full_a(s),  1);   // producer's single arrive (+tx)
            mbar_init(empty_a(s), 8);   // one arrive per consumer warp
        }
    }
    __syncthreads();

    if (t >= 256) {
        // ---- Producer (single thread of warp 8) ----
        if (t == 256) {
            for (int i = 0; i < NROWS; ++i) {
                const int r    = y0 - 1 + i;
                const int slot = i & 7;
                mbar_wait(empty_a(slot), ((i >> 3) & 1) ^ 1); // first lap passes
                if ((unsigned)r < (unsigned)H_IN) {
                    const size_t rowstart = bp + (size_t)r * W_IN;    // float idx
                    const float* src = in + (rowstart & ~(size_t)3);  // 16B aligned
                    mbar_arrive_tx(full_a(slot), CPBYTES);
                    bulk_cp(ring0 + (uint32_t)(slot * SLOTW * 4), src,
                            CPBYTES, full_a(slot));
                } else {
                    mbar_arrive(full_a(slot));                // pad row: no data
                }
            }
        }
    } else {
        // ---- Consumers: 256 threads, cols x0 = 2t, 2t+1 ----
        const int x0 = t << 1;
        float2 h[4];

        for (int i = 0; i < NROWS; ++i) {
            const int r    = y0 - 1 + i;
            const int slot = i & 7;
            mbar_wait(full_a(slot), (i >> 3) & 1);

            float2 hh;
            if ((unsigned)r < (unsigned)H_IN) {
                const int shift = (int)((bp + (size_t)r * W_IN) & 3);
                const float* __restrict__ p = &ring[slot][0] + shift + x0; // col x0
                float xm1 = (t == 0)   ? 0.0f : p[-1];   // col x0-1 (pad at left edge)
                float a0  = p[0];
                float a1  = p[1];
                float a2  = p[2];
                float a3  = (t == 255) ? 0.0f : p[3];    // col 513 pad at right edge
                hh.x = xm1 + 3.0f * (a0 + a1) + a2;
                hh.y = a0  + 3.0f * (a1 + a2) + a3;
            } else {
                hh.x = 0.0f; hh.y = 0.0f;                // pad rows -1 / 513, 514
            }
            if ((t & 31) == 0) mbar_arrive(empty_a(slot));

            h[i & 3] = hh;
            if (i >= 3) {
                float2 ha = h[(i - 3) & 3];
                float2 hb = h[(i - 2) & 3];
                float2 hc = h[(i - 1) & 3];
                float2 o;
                o.x = (ha.x + hh.x + 3.0f * (hb.x + hc.x)) * 0.0625f;
                o.y = (ha.y + hh.y + 3.0f * (hb.y + hc.y)) * 0.0625f;
                *reinterpret_cast<float2*>(op + (size_t)(y0 + i - 3) * W_OUT + x0) = o;
            }
        }
    }
}

extern "C" void kernel_launch(void* const* d_in, const int* in_sizes, int n_in,
                              void* d_out, int out_size)
{
    const float* in  = (const float*)d_in[0];
    float*       out = (float*)d_out;
    // d_in[1] is the 4x4 FIR buffer: fixed normalized [1,3,3,1] outer product
    // * factor^2 == ([1,3,3,1] ⊗ [1,3,3,1]) / 16, folded into the constants.

    dim3 grid(H_OUT / STRIP, NPLANE);   // (8, 512)
    blur_bulk_kernel<<<grid, 288>>>(in, out);
}

// round 16
// speedup vs baseline: 1.4665x; 1.0844x over previous
#include <cuda_runtime.h>
#include <cstdint>

// Blur: depthwise 4x4 FIR (separable [1,3,3,1] ⊗ [1,3,3,1] / 16), pad (1,1).
// Input (4,128,513,513) f32 -> Output (4,128,512,512) f32.
//
// Round-16: R15's bulk-async producer (1 UBLKCP per input row into an 8-deep
// smem ring, mbarrier handshake) + a rebuilt lean consumer:
//  - 128 consumer threads, 4 output cols each: 2-3 aligned conflict-free
//    LDS.128 per row (vs 5 conflicted scalar LDS per 2 cols in R15).
//  - Row-start alignment shift s = (plane - 1 + i) mod 4 cycles with i, so
//    the consumer is templated on P3=(plane+3)&3 and unrolled by 4: every
//    body has a COMPILE-TIME shift -> register select, no per-row math.
//  - Vertical FIR ring with static indices; incremented output pointer;
//    pad rows via one predicated multiply (stale slot data is finite).

#define W_IN   513
#define H_IN   513
#define W_OUT  512
#define STRIP  64
#define NROWS  67             // rows y0-1 .. y0+65
#define SLOTW  528            // floats per ring slot (2112 B)
#define NSLOT  8
#define NPLANE 512
#define CPBYTES 2064

__device__ __forceinline__ void mbar_init(uint32_t a, uint32_t c) {
    asm volatile("mbarrier.init.shared.b64 [%0], %1;" :: "r"(a), "r"(c) : "memory");
}
__device__ __forceinline__ void mbar_arrive(uint32_t a) {
    asm volatile("mbarrier.arrive.shared.b64 _, [%0];" :: "r"(a) : "memory");
}
__device__ __forceinline__ void mbar_arrive_tx(uint32_t a, uint32_t b) {
    asm volatile("mbarrier.arrive.expect_tx.shared.b64 _, [%0], %1;"
                 :: "r"(a), "r"(b) : "memory");
}
__device__ __forceinline__ void mbar_wait(uint32_t a, uint32_t ph) {
    asm volatile(
        "{\n\t.reg .pred P;\n\t"
        "W_%=:\n\t"
        "mbarrier.try_wait.parity.acquire.cta.shared::cta.b64 P, [%0], %1, 0x989680;\n\t"
        "@!P bra W_%=;\n\t}"
        :: "r"(a), "r"(ph) : "memory");
}
__device__ __forceinline__ void bulk_cp(uint32_t d, const void* s,
                                        uint32_t b, uint32_t mb) {
    asm volatile(
        "cp.async.bulk.shared::cta.global.mbarrier::complete_tx::bytes "
        "[%0], [%1], %2, [%3];"
        :: "r"(d), "l"(s), "r"(b), "r"(mb) : "memory");
}

// Horizontal FIR for cols 4t..4t+3 from slot sl, compile-time shift SH.
// buf[j] = in[rowAligned + j]; col c lives at j = c + SH. Window cols
// 4t-1..4t+5. All LDS.128 aligned; consecutive threads -> conflict-free.
template<int SH>
__device__ __forceinline__ float4 hread(const float* __restrict__ sl, int t)
{
    float w0, w1, w2, w3, w4, w5, w6;
    if constexpr (SH == 1) {
        float4 A = *reinterpret_cast<const float4*>(sl + 4 * t);
        float4 B = *reinterpret_cast<const float4*>(sl + 4 * t + 4);
        w0=A.x; w1=A.y; w2=A.z; w3=A.w; w4=B.x; w5=B.y; w6=B.z;
    } else if constexpr (SH == 2) {
        float4 A = *reinterpret_cast<const float4*>(sl + 4 * t);
        float4 B = *reinterpret_cast<const float4*>(sl + 4 * t + 4);
        w0=A.y; w1=A.z; w2=A.w; w3=B.x; w4=B.y; w5=B.z; w6=B.w;
    } else if constexpr (SH == 3) {
        float4 A = *reinterpret_cast<const float4*>(sl + 4 * t);
        float4 B = *reinterpret_cast<const float4*>(sl + 4 * t + 4);
        float4 C = *reinterpret_cast<const float4*>(sl + 4 * t + 8);
        w0=A.z; w1=A.w; w2=B.x; w3=B.y; w4=B.z; w5=B.w; w6=C.x;
    } else {                       // SH == 0
        int tm = (t == 0) ? 0 : t - 1;
        float4 A = *reinterpret_cast<const float4*>(sl + 4 * tm);
        float4 B = *reinterpret_cast<const float4*>(sl + 4 * t);
        float4 C = *reinterpret_cast<const float4*>(sl + 4 * t + 4);
        w0=A.w; w1=B.x; w2=B.y; w3=B.z; w4=B.w; w5=C.x; w6=C.y;
    }
    if (t == 0)   w0 = 0.0f;       // col -1: image pad
    if (t == 127) w6 = 0.0f;       // col 513: image pad
    float4 h;
    h.x = w0 + 3.0f * (w1 + w2) + w3;
    h.y = w1 + 3.0f * (w2 + w3) + w4;
    h.z = w2 + 3.0f * (w3 + w4) + w5;
    h.w = w3 + 3.0f * (w4 + w5) + w6;
    return h;
}

template<int P3>
__device__ __forceinline__ void run_consumer(
    const float* __restrict__ ring, uint32_t mb0, int t, int y0,
    float* __restrict__ op)
{
    auto full_a  = [&](int s) { return mb0 + (uint32_t)(s * 8); };
    auto empty_a = [&](int s) { return mb0 + (uint32_t)((NSLOT + s) * 8); };
    const bool lead = ((t & 31) == 0);

    float4 h[4];

    // Prologue i = 0..2 (rows y0-1, y0, y0+1); shift_i = (P3+i)&3.
    mbar_wait(full_a(0), 0);
    if (y0 == 0) h[0] = make_float4(0.f, 0.f, 0.f, 0.f);   // pad row, smem uninit
    else         h[0] = hread<(P3 + 0) & 3>(ring + 0 * SLOTW, t);
    if (lead) mbar_arrive(empty_a(0));
    mbar_wait(full_a(1), 0);
    h[1] = hread<(P3 + 1) & 3>(ring + 1 * SLOTW, t);
    if (lead) mbar_arrive(empty_a(1));
    mbar_wait(full_a(2), 0);
    h[2] = hread<(P3 + 2) & 3>(ring + 2 * SLOTW, t);
    if (lead) mbar_arrive(empty_a(2));

    float* optr = op + (size_t)y0 * W_OUT + 4 * t;

#define STEP(J)                                                               \
    {                                                                         \
        const int i    = ib + (J);                                            \
        const int slot = i & 7;                                               \
        mbar_wait(full_a(slot), (i >> 3) & 1);                                \
        float4 hd = hread<(P3 + 3 + (J)) & 3>(ring + slot * SLOTW, t);        \
        if (lead) mbar_arrive(empty_a(slot));                                 \
        const float rm = (y0 - 1 + i < H_IN) ? 1.0f : 0.0f;                   \
        hd.x *= rm; hd.y *= rm; hd.z *= rm; hd.w *= rm;                       \
        float4 pa = h[(0 + (J)) & 3];                                         \
        float4 pb = h[(1 + (J)) & 3];                                         \
        float4 pc = h[(2 + (J)) & 3];                                         \
        h[(3 + (J)) & 3] = hd;                                                \
        float4 o;                                                             \
        o.x = (pa.x + hd.x + 3.0f * (pb.x + pc.x)) * 0.0625f;                 \
        o.y = (pa.y + hd.y + 3.0f * (pb.y + pc.y)) * 0.0625f;                 \
        o.z = (pa.z + hd.z + 3.0f * (pb.z + pc.z)) * 0.0625f;                 \
        o.w = (pa.w + hd.w + 3.0f * (pb.w + pc.w)) * 0.0625f;                 \
        *reinterpret_cast<float4*>(optr + (J) * W_OUT) = o;                   \
    }

    for (int ib = 3; ib < 3 + STRIP; ib += 4) {   // ib ≡ 3 (mod 4)
        STEP(0); STEP(1); STEP(2); STEP(3);
        optr += 4 * W_OUT;
    }
#undef STEP
}

__global__ __launch_bounds__(160)
void blur_bulk2_kernel(const float* __restrict__ in, float* __restrict__ out)
{
    __shared__ __align__(16) float ring[NSLOT][SLOTW];            // 16.5 KB
    __shared__ __align__(8)  unsigned long long mbar[2 * NSLOT];

    const int t     = threadIdx.x;        // 0..127 consume, 128..159 produce
    const int plane = blockIdx.y;
    const int y0    = blockIdx.x * STRIP;

    const size_t bp = (size_t)plane * (W_IN * H_IN);
    const uint32_t ring0 = (uint32_t)__cvta_generic_to_shared(&ring[0][0]);
    const uint32_t mb0   = (uint32_t)__cvta_generic_to_shared(&mbar[0]);

    if (t == 0) {
        #pragma unroll
        for (int s = 0; s < NSLOT; ++s) {
            mbar_init(mb0 + s * 8, 1);               // full: producer arrive(+tx)
            mbar_init(mb0 + (NSLOT + s) * 8, 4);     // empty: 4 consumer warps
        }
    }
    __syncthreads();

    if (t >= 128) {
        if (t == 128) {                              // ---- producer ----
            for (int i = 0; i < NROWS; ++i) {
                const int r    = y0 - 1 + i;
                const int slot = i & 7;
                mbar_wait(mb0 + (NSLOT + slot) * 8, ((i >> 3) & 1) ^ 1);
                if ((unsigned)r < (unsigned)H_IN) {
                    const size_t rowstart = bp + (size_t)r * W_IN;
                    const float* src = in + (rowstart & ~(size_t)3);
                    mbar_arrive_tx(mb0 + slot * 8, CPBYTES);
                    bulk_cp(ring0 + (uint32_t)(slot * SLOTW * 4), src,
                            CPBYTES, mb0 + slot * 8);
                } else {
                    mbar_arrive(mb0 + slot * 8);     // pad row: no data
                }
            }
        }
    } else {                                         // ---- consumers ----
        float* op = out + (size_t)plane * (W_OUT * (size_t)512);
        switch ((plane + 3) & 3) {
            case 0: run_consumer<0>(&ring[0][0], mb0, t, y0, op); break;
            case 1: run_consumer<1>(&ring[0][0], mb0, t, y0, op); break;
            case 2: run_consumer<2>(&ring[0][0], mb0, t, y0, op); break;
            default: run_consumer<3>(&ring[0][0], mb0, t, y0, op); break;
        }
    }
}

extern "C" void kernel_launch(void* const* d_in, const int* in_sizes, int n_in,
                              void* d_out, int out_size)
{
    const float* in  = (const float*)d_in[0];
    float*       out = (float*)d_out;
    // d_in[1] is the 4x4 FIR buffer: fixed normalized [1,3,3,1] outer product
    // * factor^2 == ([1,3,3,1] ⊗ [1,3,3,1]) / 16, folded into the constants.

    dim3 grid(512 / STRIP, NPLANE);   // (8, 512)
    blur_bulk2_kernel<<<grid, 160>>>(in, out);
}

// round 17
// speedup vs baseline: 1.5060x; 1.0269x over previous
#include <cuda_runtime.h>
#include <cstdint>

// Blur: depthwise 4x4 FIR (separable [1,3,3,1] ⊗ [1,3,3,1] / 16), pad (1,1).
// Input (4,128,513,513) f32 -> Output (4,128,512,512) f32.
//
// Round-17: R16's bulk-async architecture with 4-ROW CHUNKED copies.
// Producer: one cp.async.bulk per 4 contiguous input rows (8.2KB) into a
// 3-slot smem ring; 17 chunks cover rows y0-1..y0+66. Consumer: one
// mbarrier wait + one release per 4 output rows (4x fewer sync ops than
// R16). All chunk starts are rows ≡ y0+3 (mod 4) and y0 ≡ 0 (mod 4), so
// one compile-time shift SH=(plane+3)&3 covers the whole strip; row j of a
// chunk sits at compile-time float offset SH+513j.
// Edge handling: block (plane0,y0=0) chunk0 uses a special copy at dst
// offset 2064B (row 0 lands exactly at the SH=3 slot position of "row 0";
// the row -1 region is never read — prologue bypasses it). Last-plane
// bottom chunks clamp copy size to the buffer end; reads beyond land in
// stale-finite smem feeding only masked/zeroed taps.

#define W_IN    513
#define H_IN    513
#define W_OUT   512
#define STRIP   64
#define NCHUNK  17
#define SLOTF   2064          // floats per slot (8256 B, 16B-mult)
#define NSLOT   3
#define NPLANE  512
#define CP_FULL 8224u         // 2056 floats
#define TOTALF  134742528ll   // 512 * 513 * 513

__device__ __forceinline__ void mbar_init(uint32_t a, uint32_t c) {
    asm volatile("mbarrier.init.shared.b64 [%0], %1;" :: "r"(a), "r"(c) : "memory");
}
__device__ __forceinline__ void mbar_arrive(uint32_t a) {
    asm volatile("mbarrier.arrive.shared.b64 _, [%0];" :: "r"(a) : "memory");
}
__device__ __forceinline__ void mbar_arrive_tx(uint32_t a, uint32_t b) {
    asm volatile("mbarrier.arrive.expect_tx.shared.b64 _, [%0], %1;"
                 :: "r"(a), "r"(b) : "memory");
}
__device__ __forceinline__ void mbar_wait(uint32_t a, uint32_t ph) {
    asm volatile(
        "{\n\t.reg .pred P;\n\t"
        "W_%=:\n\t"
        "mbarrier.try_wait.parity.acquire.cta.shared::cta.b64 P, [%0], %1, 0x989680;\n\t"
        "@!P bra W_%=;\n\t}"
        :: "r"(a), "r"(ph) : "memory");
}
__device__ __forceinline__ void bulk_cp(uint32_t d, const void* s,
                                        uint32_t b, uint32_t mb) {
    asm volatile(
        "cp.async.bulk.shared::cta.global.mbarrier::complete_tx::bytes "
        "[%0], [%1], %2, [%3];"
        :: "r"(d), "l"(s), "r"(b), "r"(mb) : "memory");
}

// Horizontal FIR for cols 4t..4t+3; buf[j] = in[rowAligned + j], col c at
// j = c + SH (SH = within-16B shift). Window cols 4t-1..4t+5.
template<int SH>
__device__ __forceinline__ float4 hread(const float* __restrict__ sl, int t)
{
    float w0, w1, w2, w3, w4, w5, w6;
    if constexpr (SH == 1) {
        float4 A = *reinterpret_cast<const float4*>(sl + 4 * t);
        float4 B = *reinterpret_cast<const float4*>(sl + 4 * t + 4);
        w0=A.x; w1=A.y; w2=A.z; w3=A.w; w4=B.x; w5=B.y; w6=B.z;
    } else if constexpr (SH == 2) {
        float4 A = *reinterpret_cast<const float4*>(sl + 4 * t);
        float4 B = *reinterpret_cast<const float4*>(sl + 4 * t + 4);
        w0=A.y; w1=A.z; w2=A.w; w3=B.x; w4=B.y; w5=B.z; w6=B.w;
    } else if constexpr (SH == 3) {
        float4 A = *reinterpret_cast<const float4*>(sl + 4 * t);
        float4 B = *reinterpret_cast<const float4*>(sl + 4 * t + 4);
        float4 C = *reinterpret_cast<const float4*>(sl + 4 * t + 8);
        w0=A.z; w1=A.w; w2=B.x; w3=B.y; w4=B.z; w5=B.w; w6=C.x;
    } else {
        int tm = (t == 0) ? 0 : t - 1;
        float4 A = *reinterpret_cast<const float4*>(sl + 4 * tm);
        float4 B = *reinterpret_cast<const float4*>(sl + 4 * t);
        float4 C = *reinterpret_cast<const float4*>(sl + 4 * t + 4);
        w0=A.w; w1=B.x; w2=B.y; w3=B.z; w4=B.w; w5=C.x; w6=C.y;
    }
    if (t == 0)   w0 = 0.0f;
    if (t == 127) w6 = 0.0f;
    float4 h;
    h.x = w0 + 3.0f * (w1 + w2) + w3;
    h.y = w1 + 3.0f * (w2 + w3) + w4;
    h.z = w2 + 3.0f * (w3 + w4) + w5;
    h.w = w3 + 3.0f * (w4 + w5) + w6;
    return h;
}

template<int SH>
__device__ __forceinline__ void run_consumer(
    const float* __restrict__ ring, uint32_t mb0, int t, int y0,
    float* __restrict__ op)
{
    constexpr int S0 = SH, S1 = (SH + 1) & 3, S2 = (SH + 2) & 3, S3 = (SH + 3) & 3;
    constexpr int AL0 = (SH +    0) & ~3;
    constexpr int AL1 = (SH +  513) & ~3;
    constexpr int AL2 = (SH + 1026) & ~3;
    constexpr int AL3 = (SH + 1539) & ~3;

    auto full_a  = [&](int s) { return mb0 + (uint32_t)(s * 8); };
    auto empty_a = [&](int s) { return mb0 + (uint32_t)((NSLOT + s) * 8); };
    const bool lead = ((t & 31) == 0);

    // Prologue: chunk 0 = rows y0-1, y0, y0+1, (y0+2).
    mbar_wait(full_a(0), 0);
    float4 h0 = (y0 == 0) ? make_float4(0.f, 0.f, 0.f, 0.f)
                          : hread<S0>(ring + AL0, t);       // row y0-1
    float4 h1 = hread<S1>(ring + AL1, t);                   // row y0
    float4 h2 = hread<S2>(ring + AL2, t);                   // row y0+1

    float* optr = op + (size_t)y0 * W_OUT + 4 * t;

    int sA = 0, sB = 1, par = 0;          // chunk k slot, chunk k+1 slot, parity of k+1
    for (int k = 0; k < 16; ++k) {
        mbar_wait(full_a(sB), par);
        const float* bA = ring + sA * SLOTF;
        const float* bB = ring + sB * SLOTF;
        float4 hd0 = hread<S3>(bA + AL3, t);   // row y0+2+4k
        float4 hd1 = hread<S0>(bB + AL0, t);   // row y0+3+4k
        float4 hd2 = hread<S1>(bB + AL1, t);   // row y0+4+4k
        float4 hd3 = hread<S2>(bB + AL2, t);   // row y0+5+4k
        if (lead) mbar_arrive(empty_a(sA));

        if (y0 + 4 * k + 5 >= H_IN) {          // only last iter of last strip
            const int R = y0 + 2 + 4 * k;
            if (R     >= H_IN) hd0 = make_float4(0.f, 0.f, 0.f, 0.f);
            if (R + 1 >= H_IN) hd1 = make_float4(0.f, 0.f, 0.f, 0.f);
            if (R + 2 >= H_IN) hd2 = make_float4(0.f, 0.f, 0.f, 0.f);
            if (R + 3 >= H_IN) hd3 = make_float4(0.f, 0.f, 0.f, 0.f);
        }

        float4 o;
        o.x = (h0.x + hd0.x + 3.0f * (h1.x + h2.x)) * 0.0625f;
        o.y = (h0.y + hd0.y + 3.0f * (h1.y + h2.y)) * 0.0625f;
        o.z = (h0.z + hd0.z + 3.0f * (h1.z + h2.z)) * 0.0625f;
        o.w = (h0.w + hd0.w + 3.0f * (h1.w + h2.w)) * 0.0625f;
        *reinterpret_cast<float4*>(optr) = o;
        o.x = (h1.x + hd1.x + 3.0f * (h2.x + hd0.x)) * 0.0625f;
        o.y = (h1.y + hd1.y + 3.0f * (h2.y + hd0.y)) * 0.0625f;
        o.z = (h1.z + hd1.z + 3.0f * (h2.z + hd0.z)) * 0.0625f;
        o.w = (h1.w + hd1.w + 3.0f * (h2.w + hd0.w)) * 0.0625f;
        *reinterpret_cast<float4*>(optr + W_OUT) = o;
        o.x = (h2.x + hd2.x + 3.0f * (hd0.x + hd1.x)) * 0.0625f;
        o.y = (h2.y + hd2.y + 3.0f * (hd0.y + hd1.y)) * 0.0625f;
        o.z = (h2.z + hd2.z + 3.0f * (hd0.z + hd1.z)) * 0.0625f;
        o.w = (h2.w + hd2.w + 3.0f * (hd0.w + hd1.w)) * 0.0625f;
        *reinterpret_cast<float4*>(optr + 2 * W_OUT) = o;
        o.x = (hd0.x + hd3.x + 3.0f * (hd1.x + hd2.x)) * 0.0625f;
        o.y = (hd0.y + hd3.y + 3.0f * (hd1.y + hd2.y)) * 0.0625f;
        o.z = (hd0.z + hd3.z + 3.0f * (hd1.z + hd2.z)) * 0.0625f;
        o.w = (hd0.w + hd3.w + 3.0f * (hd1.w + hd2.w)) * 0.0625f;
        *reinterpret_cast<float4*>(optr + 3 * W_OUT) = o;

        h0 = hd1; h1 = hd2; h2 = hd3;
        optr += 4 * W_OUT;
        sA = sB;
        if (++sB == NSLOT) { sB = 0; par ^= 1; }
    }
}

__global__ __launch_bounds__(160)
void blur_chunk_kernel(const float* __restrict__ in, float* __restrict__ out)
{
    __shared__ __align__(16) float ring[NSLOT * SLOTF];          // 24.8 KB
    __shared__ __align__(8)  unsigned long long mbar[2 * NSLOT];

    const int t     = threadIdx.x;        // 0..127 consume, 128..159 produce
    const int plane = blockIdx.y;
    const int y0    = blockIdx.x * STRIP;

    const long long bp = (long long)plane * (W_IN * H_IN);
    const uint32_t ring0 = (uint32_t)__cvta_generic_to_shared(&ring[0]);
    const uint32_t mb0   = (uint32_t)__cvta_generic_to_shared(&mbar[0]);

    if (t == 0) {
        #pragma unroll
        for (int s = 0; s < NSLOT; ++s) {
            mbar_init(mb0 + s * 8, 1);               // full: producer arrive(+tx)
            mbar_init(mb0 + (NSLOT + s) * 8, 4);     // empty: 4 consumer warps
        }
    }
    __syncthreads();

    if (t >= 128) {
        if (t == 128) {                              // ---- producer ----
            const bool special = (plane == 0 && y0 == 0);
            int slot = 0, par = 1;                   // empty-wait parity per lap
            for (int c = 0; c < NCHUNK; ++c) {
                if (c >= NSLOT) mbar_wait(mb0 + (NSLOT + slot) * 8, par);
                const uint32_t fullb = mb0 + slot * 8;
                if (special && c == 0) {
                    // rows 0..2 land where SH=3 layout expects rows 0..2.
                    mbar_arrive_tx(fullb, 6176u);
                    bulk_cp(ring0 + 2064u, in, 6176u, fullb);
                } else {
                    const long long srcidx  = bp + (long long)(y0 - 1 + 4 * c) * W_IN;
                    const long long aligned = srcidx & ~3ll;
                    const long long avail   = TOTALF - aligned;      // floats
                    const uint32_t  bytes   =
                        (avail < 2056ll) ? (uint32_t)(avail * 4) : CP_FULL;
                    mbar_arrive_tx(fullb, bytes);
                    bulk_cp(ring0 + (uint32_t)(slot * SLOTF * 4),
                            in + aligned, bytes, fullb);
                }
                if (++slot == NSLOT) { slot = 0; par ^= 1; }
            }
        }
    } else {                                         // ---- consumers ----
        float* op = out + (size_t)plane * (W_OUT * (size_t)512);
        switch ((plane + 3) & 3) {                   // y0 ≡ 0 (mod 4)
            case 0:  run_consumer<0>(ring, mb0, t, y0, op); break;
            case 1:  run_consumer<1>(ring, mb0, t, y0, op); break;
            case 2:  run_consumer<2>(ring, mb0, t, y0, op); break;
            default: run_consumer<3>(ring, mb0, t, y0, op); break;
        }
    }
}

extern "C" void kernel_launch(void* const* d_in, const int* in_sizes, int n_in,
                              void* d_out, int out_size)
{
    const float* in  = (const float*)d_in[0];
    float*       out = (float*)d_out;
    // d_in[1] is the 4x4 FIR buffer: fixed normalized [1,3,3,1] outer product
    // * factor^2 == ([1,3,3,1] ⊗ [1,3,3,1]) / 16, folded into the constants.

    dim3 grid(512 / STRIP, NPLANE);   // (8, 512)
    blur_chunk_kernel<<<grid, 160>>>(in, out);
}